// round 2
// baseline (speedup 1.0000x reference)
#include <cuda_runtime.h>
#include <math.h>

#define PN 22
#define DN 3
#define HN 64
#define LN 5
#define NWARP 11
#define NTHREADS 352
#define CRC 3.0f       /* 15.0 / 5 layers */
#define LOG2M 7.0f
#define EGROUPS 6      /* ceil(21/4) groups of 4 edges per node */

/* ---- shared memory layout (floats) ---- */
constexpr int OFF_EW1 = 0;                     /* 130*64 */
constexpr int OFF_EW2 = OFF_EW1 + 130 * 64;    /* 64*64  */
constexpr int OFF_NW1 = OFF_EW2 + 64 * 64;     /* 128*64 */
constexpr int OFF_NW2 = OFF_NW1 + 128 * 64;    /* 64*64  */
constexpr int OFF_CW1 = OFF_NW2 + 64 * 64;     /* 64*64  */
constexpr int OFF_CW2 = OFF_CW1 + 64 * 64;     /* 64 */
constexpr int OFF_AW  = OFF_CW2 + 64;          /* 64 */
constexpr int OFF_EB1 = OFF_AW + 64;
constexpr int OFF_EB2 = OFF_EB1 + 64;
constexpr int OFF_NB1 = OFF_EB2 + 64;
constexpr int OFF_NB2 = OFF_NB1 + 64;
constexpr int OFF_CB1 = OFF_NB2 + 64;
constexpr int OFF_H   = OFF_CB1 + 64;          /* 22*64 */
constexpr int OFF_HR  = OFF_H + PN * HN;       /* 22*64 */
constexpr int OFF_HC  = OFF_HR + PN * HN;      /* 22*64 */
constexpr int OFF_EA  = OFF_HC + PN * HN;      /* 22*22 = 484 */
constexpr int OFF_WB  = OFF_EA + PN * PN;      /* 11 warps * 4 edges * 64 */
constexpr int OFF_CRD = OFF_WB + NWARP * 4 * HN;   /* 22*3 */
constexpr int OFF_CR0 = OFF_CRD + PN * DN;         /* 22*3 */
constexpr int OFF_VEL = OFF_CR0 + PN * DN;         /* 22*3 */
constexpr int OFF_MEAN = OFF_VEL + PN * DN;        /* 4 */
constexpr int OFF_AB  = OFF_MEAN + 4;              /* 1 */
constexpr int SMEM_FLOATS = OFF_AB + 1;

__device__ __forceinline__ float siluf(float v) { return v / (1.f + __expf(-v)); }
__device__ __forceinline__ float sigmf_(float v) { return 1.f / (1.f + __expf(-v)); }

/* 4-edge-batched GEMV: u[e][0..1] += buf[e][:] @ W[:, 2*lane:2*lane+2]
   buf: 4 contiguous 64-float activation rows (16B aligned), W: 64x64 row-major */
__device__ __forceinline__ void gemv4x64(const float* __restrict__ Wm,
                                         const float* __restrict__ buf,
                                         const int lane, float u[4][2])
{
#pragma unroll
    for (int k = 0; k < HN; k += 4) {
        const float4 a0 = *(const float4*)&buf[0 * HN + k];
        const float4 a1 = *(const float4*)&buf[1 * HN + k];
        const float4 a2 = *(const float4*)&buf[2 * HN + k];
        const float4 a3 = *(const float4*)&buf[3 * HN + k];
        { const float2 wv = *(const float2*)&Wm[(k + 0) * HN + 2 * lane];
          u[0][0] += a0.x * wv.x; u[0][1] += a0.x * wv.y;
          u[1][0] += a1.x * wv.x; u[1][1] += a1.x * wv.y;
          u[2][0] += a2.x * wv.x; u[2][1] += a2.x * wv.y;
          u[3][0] += a3.x * wv.x; u[3][1] += a3.x * wv.y; }
        { const float2 wv = *(const float2*)&Wm[(k + 1) * HN + 2 * lane];
          u[0][0] += a0.y * wv.x; u[0][1] += a0.y * wv.y;
          u[1][0] += a1.y * wv.x; u[1][1] += a1.y * wv.y;
          u[2][0] += a2.y * wv.x; u[2][1] += a2.y * wv.y;
          u[3][0] += a3.y * wv.x; u[3][1] += a3.y * wv.y; }
        { const float2 wv = *(const float2*)&Wm[(k + 2) * HN + 2 * lane];
          u[0][0] += a0.z * wv.x; u[0][1] += a0.z * wv.y;
          u[1][0] += a1.z * wv.x; u[1][1] += a1.z * wv.y;
          u[2][0] += a2.z * wv.x; u[2][1] += a2.z * wv.y;
          u[3][0] += a3.z * wv.x; u[3][1] += a3.z * wv.y; }
        { const float2 wv = *(const float2*)&Wm[(k + 3) * HN + 2 * lane];
          u[0][0] += a0.w * wv.x; u[0][1] += a0.w * wv.y;
          u[1][0] += a1.w * wv.x; u[1][1] += a1.w * wv.y;
          u[2][0] += a2.w * wv.x; u[2][1] += a2.w * wv.y;
          u[3][0] += a3.w * wv.x; u[3][1] += a3.w * wv.y; }
    }
}

__global__ __launch_bounds__(NTHREADS, 1)
void egnn_kernel(const float* __restrict__ t, const float* __restrict__ x,
                 const float* __restrict__ embW, const float* __restrict__ embb,
                 const float* __restrict__ ew1, const float* __restrict__ eb1,
                 const float* __restrict__ ew2, const float* __restrict__ eb2,
                 const float* __restrict__ nw1, const float* __restrict__ nb1,
                 const float* __restrict__ nw2, const float* __restrict__ nb2,
                 const float* __restrict__ cw1, const float* __restrict__ cb1,
                 const float* __restrict__ cw2, const float* __restrict__ aw,
                 const float* __restrict__ ab, float* __restrict__ out)
{
    extern __shared__ float sm[];
    const int tid = threadIdx.x;
    const int b = blockIdx.x;
    const int w = tid >> 5;
    const int lane = tid & 31;

    /* ---- init: coords, h, edge_attr ---- */
    for (int idx = tid; idx < PN * DN; idx += NTHREADS) {
        const float c = x[b * (PN * DN) + idx];
        sm[OFF_CRD + idx] = c;
        sm[OFF_CR0 + idx] = c;
    }
    const float tb = t[b];
    for (int idx = tid; idx < PN * HN; idx += NTHREADS) {
        const int i = idx >> 6, o = idx & 63;
        sm[OFF_H + idx] = embW[i * HN + o] + tb * embW[22 * HN + o]
                        + LOG2M * embW[23 * HN + o] + embb[o];
    }
    __syncthreads();
    for (int idx = tid; idx < PN * PN; idx += NTHREADS) {
        const int i = idx / PN, j = idx % PN;
        const float dx = sm[OFF_CRD + i * 3 + 0] - sm[OFF_CRD + j * 3 + 0];
        const float dy = sm[OFF_CRD + i * 3 + 1] - sm[OFF_CRD + j * 3 + 1];
        const float dz = sm[OFF_CRD + i * 3 + 2] - sm[OFF_CRD + j * 3 + 2];
        sm[OFF_EA + idx] = dx * dx + dy * dy + dz * dz;
    }
    /* weight-copy barrier below orders EA before use */

    float* const wb = &sm[OFF_WB + w * (4 * HN)];

    for (int l = 0; l < LN; ++l) {
        /* ---- stage this layer's weights into shared ---- */
        {
            const float* s1 = ew1 + l * 130 * 64;
            for (int q = tid; q < 130 * 64; q += NTHREADS) sm[OFF_EW1 + q] = s1[q];
            const float* s2 = ew2 + l * 4096;
            for (int q = tid; q < 4096; q += NTHREADS) sm[OFF_EW2 + q] = s2[q];
            const float* s3 = nw1 + l * 8192;
            for (int q = tid; q < 8192; q += NTHREADS) sm[OFF_NW1 + q] = s3[q];
            const float* s4 = nw2 + l * 4096;
            for (int q = tid; q < 4096; q += NTHREADS) sm[OFF_NW2 + q] = s4[q];
            const float* s5 = cw1 + l * 4096;
            for (int q = tid; q < 4096; q += NTHREADS) sm[OFF_CW1 + q] = s5[q];
            if (tid < 64) {
                sm[OFF_CW2 + tid] = cw2[l * 64 + tid];
                sm[OFF_AW + tid]  = aw[l * 64 + tid];
                sm[OFF_EB1 + tid] = eb1[l * 64 + tid];
                sm[OFF_EB2 + tid] = eb2[l * 64 + tid];
                sm[OFF_NB1 + tid] = nb1[l * 64 + tid];
                sm[OFF_NB2 + tid] = nb2[l * 64 + tid];
                sm[OFF_CB1 + tid] = cb1[l * 64 + tid];
            }
            if (tid == 0) sm[OFF_AB] = ab[l];
        }
        __syncthreads();

        /* ---- phase 1: per-node projections Hr = h@W1[0:64], Hc = h@W1[64:128] ---- */
#pragma unroll
        for (int nn = 0; nn < 2; ++nn) {
            const int i = w * 2 + nn;
            float r0 = 0.f, r1 = 0.f, c0 = 0.f, c1 = 0.f;
#pragma unroll 8
            for (int k = 0; k < HN; ++k) {
                const float a = sm[OFF_H + i * HN + k];
                const float2 wr = *(const float2*)&sm[OFF_EW1 + k * HN + 2 * lane];
                const float2 wc = *(const float2*)&sm[OFF_EW1 + (64 + k) * HN + 2 * lane];
                r0 += a * wr.x; r1 += a * wr.y;
                c0 += a * wc.x; c1 += a * wc.y;
            }
            sm[OFF_HR + i * HN + 2 * lane]     = r0;
            sm[OFF_HR + i * HN + 2 * lane + 1] = r1;
            sm[OFF_HC + i * HN + 2 * lane]     = c0;
            sm[OFF_HC + i * HN + 2 * lane + 1] = c1;
        }
        __syncthreads();

        /* ---- phase 2: edges (4 at a time per warp), accumulate agg + coord delta ---- */
        float aggL[2][2];
        float dcd[2][3];
#pragma unroll
        for (int nn = 0; nn < 2; ++nn) {
            const int i = w * 2 + nn;
            float agg0 = 0.f, agg1 = 0.f, dc0 = 0.f, dc1 = 0.f, dc2 = 0.f;
            const float cix = sm[OFF_CRD + i * 3 + 0];
            const float ciy = sm[OFF_CRD + i * 3 + 1];
            const float ciz = sm[OFF_CRD + i * 3 + 2];
            const float hr0 = sm[OFF_HR + i * HN + 2 * lane];
            const float hr1 = sm[OFF_HR + i * HN + 2 * lane + 1];
            const float w1280 = sm[OFF_EW1 + 128 * HN + 2 * lane];
            const float w1281 = sm[OFF_EW1 + 128 * HN + 2 * lane + 1];
            const float w1290 = sm[OFF_EW1 + 129 * HN + 2 * lane];
            const float w1291 = sm[OFF_EW1 + 129 * HN + 2 * lane + 1];
            const float b10 = sm[OFF_EB1 + 2 * lane];
            const float b11 = sm[OFF_EB1 + 2 * lane + 1];
            const float bb0 = sm[OFF_EB2 + 2 * lane];
            const float bb1 = sm[OFF_EB2 + 2 * lane + 1];
            const float cb0 = sm[OFF_CB1 + 2 * lane];
            const float cb1v = sm[OFF_CB1 + 2 * lane + 1];
            const float aw0 = sm[OFF_AW + 2 * lane];
            const float aw1 = sm[OFF_AW + 2 * lane + 1];
            const float cw20 = sm[OFF_CW2 + 2 * lane];
            const float cw21 = sm[OFF_CW2 + 2 * lane + 1];
            const float abv = sm[OFF_AB];

            for (int g = 0; g < EGROUPS; ++g) {
                float valid[4], ndx[4], ndy[4], ndz[4];
                /* pre-activation + silu -> stage t1 into wb */
#pragma unroll
                for (int e = 0; e < 4; ++e) {
                    const int jraw = g * 4 + e;
                    int j = (jraw < i) ? jraw : jraw + 1;
                    const float v = (j < PN) ? 1.f : 0.f;
                    if (j >= PN) j = i;       /* safe self-edge dummy */
                    valid[e] = v;
                    const float dx = cix - sm[OFF_CRD + j * 3 + 0];
                    const float dy = ciy - sm[OFF_CRD + j * 3 + 1];
                    const float dz = ciz - sm[OFF_CRD + j * 3 + 2];
                    const float radial = dx * dx + dy * dy + dz * dz;
                    const float inv = 1.f / (sqrtf(radial) + 1.f);
                    ndx[e] = dx * inv; ndy[e] = dy * inv; ndz[e] = dz * inv;
                    const float eav = sm[OFF_EA + i * PN + j];
                    const float p0 = hr0 + sm[OFF_HC + j * HN + 2 * lane]
                                   + radial * w1280 + eav * w1290 + b10;
                    const float p1 = hr1 + sm[OFF_HC + j * HN + 2 * lane + 1]
                                   + radial * w1281 + eav * w1291 + b11;
                    wb[e * HN + 2 * lane]     = siluf(p0);
                    wb[e * HN + 2 * lane + 1] = siluf(p1);
                }
                __syncwarp();

                /* GEMV2: m = silu(t1 @ ew2 + eb2), then attention gate */
                float u[4][2];
#pragma unroll
                for (int e = 0; e < 4; ++e) { u[e][0] = bb0; u[e][1] = bb1; }
                gemv4x64(&sm[OFF_EW2], wb, lane, u);

                float m0[4], m1[4];
#pragma unroll
                for (int e = 0; e < 4; ++e) { m0[e] = siluf(u[e][0]); m1[e] = siluf(u[e][1]); }
#pragma unroll
                for (int e = 0; e < 4; ++e) {
                    float part = m0[e] * aw0 + m1[e] * aw1;
#pragma unroll
                    for (int off = 16; off; off >>= 1)
                        part += __shfl_xor_sync(0xffffffffu, part, off);
                    const float gate = sigmf_(part + abv);
                    m0[e] *= gate; m1[e] *= gate;
                }
                __syncwarp();   /* everyone finished reading t1 */
#pragma unroll
                for (int e = 0; e < 4; ++e) {
                    wb[e * HN + 2 * lane]     = m0[e];
                    wb[e * HN + 2 * lane + 1] = m1[e];
                }
                __syncwarp();

                /* GEMV3: c1 = silu(m @ cw1 + cb1); scalar = tanh(c1 @ cw2)*CR */
                float q[4][2];
#pragma unroll
                for (int e = 0; e < 4; ++e) { q[e][0] = cb0; q[e][1] = cb1v; }
                gemv4x64(&sm[OFF_CW1], wb, lane, q);

#pragma unroll
                for (int e = 0; e < 4; ++e) {
                    float s = siluf(q[e][0]) * cw20 + siluf(q[e][1]) * cw21;
#pragma unroll
                    for (int off = 16; off; off >>= 1)
                        s += __shfl_xor_sync(0xffffffffu, s, off);
                    const float scal = tanhf(s) * CRC;
                    dc0 += ndx[e] * scal;
                    dc1 += ndy[e] * scal;
                    dc2 += ndz[e] * scal;
                    agg0 += m0[e] * valid[e];
                    agg1 += m1[e] * valid[e];
                }
                __syncwarp();   /* reads of m done before next group rewrites wb */
            }
            aggL[nn][0] = agg0; aggL[nn][1] = agg1;
            dcd[nn][0] = dc0; dcd[nn][1] = dc1; dcd[nn][2] = dc2;
        }
        __syncthreads();   /* all reads of coord/Hr/Hc complete */

        /* ---- phase 3: coord update + node MLP (owner warp, no atomics) ---- */
#pragma unroll
        for (int nn = 0; nn < 2; ++nn) {
            const int i = w * 2 + nn;
            if (lane == 0) {
                sm[OFF_CRD + i * 3 + 0] += dcd[nn][0];
                sm[OFF_CRD + i * 3 + 1] += dcd[nn][1];
                sm[OFF_CRD + i * 3 + 2] += dcd[nn][2];
            }
            wb[2 * lane] = aggL[nn][0];
            wb[2 * lane + 1] = aggL[nn][1];
            __syncwarp();
            float g0 = sm[OFF_NB1 + 2 * lane], g1 = sm[OFF_NB1 + 2 * lane + 1];
#pragma unroll 8
            for (int k = 0; k < HN; ++k) {
                const float a = sm[OFF_H + i * HN + k];
                const float2 wv = *(const float2*)&sm[OFF_NW1 + k * HN + 2 * lane];
                g0 += a * wv.x; g1 += a * wv.y;
            }
#pragma unroll 8
            for (int k = 0; k < HN; ++k) {
                const float a = wb[k];
                const float2 wv = *(const float2*)&sm[OFF_NW1 + (HN + k) * HN + 2 * lane];
                g0 += a * wv.x; g1 += a * wv.y;
            }
            g0 = siluf(g0); g1 = siluf(g1);
            __syncwarp();
            wb[2 * lane] = g0; wb[2 * lane + 1] = g1;
            __syncwarp();
            float o0 = sm[OFF_NB2 + 2 * lane], o1 = sm[OFF_NB2 + 2 * lane + 1];
#pragma unroll 8
            for (int k = 0; k < HN; ++k) {
                const float a = wb[k];
                const float2 wv = *(const float2*)&sm[OFF_NW2 + k * HN + 2 * lane];
                o0 += a * wv.x; o1 += a * wv.y;
            }
            sm[OFF_H + i * HN + 2 * lane]     += o0;
            sm[OFF_H + i * HN + 2 * lane + 1] += o1;
            __syncwarp();
        }
        __syncthreads();
    } /* layer loop */

    /* ---- velocity + mean removal ---- */
    for (int idx = tid; idx < PN * DN; idx += NTHREADS)
        sm[OFF_VEL + idx] = sm[OFF_CRD + idx] - sm[OFF_CR0 + idx];
    __syncthreads();
    if (tid < DN) {
        float s = 0.f;
        for (int i = 0; i < PN; ++i) s += sm[OFF_VEL + i * 3 + tid];
        sm[OFF_MEAN + tid] = s * (1.f / PN);
    }
    __syncthreads();
    for (int idx = tid; idx < PN * DN; idx += NTHREADS)
        out[b * (PN * DN) + idx] = sm[OFF_VEL + idx] - sm[OFF_MEAN + idx % 3];
}

extern "C" void kernel_launch(void* const* d_in, const int* in_sizes, int n_in,
                              void* d_out, int out_size)
{
    const float* t    = (const float*)d_in[0];
    const float* x    = (const float*)d_in[1];
    const float* embW = (const float*)d_in[2];
    const float* embb = (const float*)d_in[3];
    /* d_in[4] out_W, d_in[5] out_b: dead code (output depends only on coords) */
    const float* ew1  = (const float*)d_in[6];
    const float* eb1  = (const float*)d_in[7];
    const float* ew2  = (const float*)d_in[8];
    const float* eb2  = (const float*)d_in[9];
    const float* nw1  = (const float*)d_in[10];
    const float* nb1  = (const float*)d_in[11];
    const float* nw2  = (const float*)d_in[12];
    const float* nb2  = (const float*)d_in[13];
    const float* cw1  = (const float*)d_in[14];
    const float* cb1  = (const float*)d_in[15];
    const float* cw2  = (const float*)d_in[16];
    const float* aw   = (const float*)d_in[17];
    const float* ab   = (const float*)d_in[18];
    /* d_in[19] rows, d_in[20] cols: structure is known analytically */

    const int B = in_sizes[0];
    const size_t smem = (size_t)SMEM_FLOATS * sizeof(float);
    cudaFuncSetAttribute(egnn_kernel, cudaFuncAttributeMaxDynamicSharedMemorySize, (int)smem);
    egnn_kernel<<<B, NTHREADS, smem>>>(t, x, embW, embb, ew1, eb1, ew2, eb2,
                                       nw1, nb1, nw2, nb2, cw1, cb1, cw2, aw, ab,
                                       (float*)d_out);
}

// round 3
// speedup vs baseline: 1.0073x; 1.0073x over previous
#include <cuda_runtime.h>
#include <math.h>

#define PN 22
#define DN 3
#define HN 64
#define LN 5
#define NWARP 11
#define NTHREADS 352
#define CRC 3.0f       /* 15.0 / 5 layers */
#define LOG2M 7.0f

typedef unsigned long long ull;

/* ---- shared memory layout (floats) ---- */
constexpr int OFF_EW1 = 0;                     /* 130*64 = 8320 */
constexpr int OFF_EW2 = 8320;                  /* 64*64 */
constexpr int OFF_NW1 = 12416;                 /* 128*64 */
constexpr int OFF_NW2 = 20608;                 /* 64*64 */
constexpr int OFF_CW1 = 24704;                 /* 64*64 */
constexpr int OFF_CW2 = 28800;                 /* 64 */
constexpr int OFF_AW  = 28864;
constexpr int OFF_EB1 = 28928;
constexpr int OFF_EB2 = 28992;
constexpr int OFF_NB1 = 29056;
constexpr int OFF_NB2 = 29120;
constexpr int OFF_CB1 = 29184;
constexpr int OFF_H   = 29248;                 /* 22*64 */
constexpr int OFF_HR  = 30656;                 /* 22*64 */
constexpr int OFF_HC  = 32064;                 /* 22*64 */
constexpr int OFF_EA  = 33472;                 /* 22*22=484, pad to 488 */
constexpr int OFF_WB  = 33960;                 /* 11 warps * 8 edges * 64 ull = 11264 floats */
constexpr int OFF_CRD = 45224;                 /* 66 -> pad 68 */
constexpr int OFF_CR0 = 45292;
constexpr int OFF_VEL = 45360;
constexpr int OFF_MEAN = 45428;
constexpr int OFF_AB  = 45432;
constexpr int SMEM_FLOATS = 45436;             /* 181,744 bytes */

__device__ __forceinline__ float siluf(float v) { return v / (1.f + __expf(-v)); }
__device__ __forceinline__ float sigmf_(float v) { return 1.f / (1.f + __expf(-v)); }

__device__ __forceinline__ void ffma2(ull& d, ull a, ull b) {
    asm("fma.rn.f32x2 %0, %1, %2, %0;" : "+l"(d) : "l"(a), "l"(b));
}
__device__ __forceinline__ ull add2(ull a, ull b) {
    ull r; asm("add.rn.f32x2 %0, %1, %2;" : "=l"(r) : "l"(a), "l"(b)); return r;
}
__device__ __forceinline__ ull pack2(float x, float y) {
    ull r; asm("mov.b64 %0, {%1, %2};" : "=l"(r) : "f"(x), "f"(y)); return r;
}
__device__ __forceinline__ void unpack2(ull v, float& x, float& y) {
    asm("mov.b64 {%0, %1}, %2;" : "=f"(x), "=f"(y) : "l"(v));
}

/* 8-edge-batched GEMV with packed FFMA2.
   Wm: 64x64 row-major (floats). act: 8 rows of 64 ull, each ull = {a,a} duplicated.
   u[e] accumulates output cols (2*lane, 2*lane+1) as f32x2. */
__device__ __forceinline__ void gemv8(const float* __restrict__ Wm,
                                      const ull* __restrict__ act,
                                      const int lane, ull u[8])
{
#pragma unroll 8
    for (int k = 0; k < HN; k += 2) {
        const ull w0 = *(const ull*)&Wm[k * HN + 2 * lane];
        const ull w1 = *(const ull*)&Wm[(k + 1) * HN + 2 * lane];
#pragma unroll
        for (int e = 0; e < 8; ++e) {
            const ulonglong2 a = *(const ulonglong2*)&act[e * HN + k];
            ffma2(u[e], a.x, w0);
            ffma2(u[e], a.y, w1);
        }
    }
}

__global__ __launch_bounds__(NTHREADS, 1)
void egnn_kernel(const float* __restrict__ t, const float* __restrict__ x,
                 const float* __restrict__ embW, const float* __restrict__ embb,
                 const float* __restrict__ ew1, const float* __restrict__ eb1,
                 const float* __restrict__ ew2, const float* __restrict__ eb2,
                 const float* __restrict__ nw1, const float* __restrict__ nb1,
                 const float* __restrict__ nw2, const float* __restrict__ nb2,
                 const float* __restrict__ cw1, const float* __restrict__ cb1,
                 const float* __restrict__ cw2, const float* __restrict__ aw,
                 const float* __restrict__ ab, float* __restrict__ out)
{
    extern __shared__ float sm[];
    const int tid = threadIdx.x;
    const int b = blockIdx.x;
    const int w = tid >> 5;
    const int lane = tid & 31;

    /* ---- init: coords, h ---- */
    for (int idx = tid; idx < PN * DN; idx += NTHREADS) {
        const float c = x[b * (PN * DN) + idx];
        sm[OFF_CRD + idx] = c;
        sm[OFF_CR0 + idx] = c;
    }
    const float tb = t[b];
    for (int idx = tid; idx < PN * HN; idx += NTHREADS) {
        const int i = idx >> 6, o = idx & 63;
        sm[OFF_H + idx] = embW[i * HN + o] + tb * embW[22 * HN + o]
                        + LOG2M * embW[23 * HN + o] + embb[o];
    }
    __syncthreads();
    /* edge_attr = initial squared distances */
    for (int idx = tid; idx < PN * PN; idx += NTHREADS) {
        const int i = idx / PN, j = idx % PN;
        const float dx = sm[OFF_CRD + i * 3 + 0] - sm[OFF_CRD + j * 3 + 0];
        const float dy = sm[OFF_CRD + i * 3 + 1] - sm[OFF_CRD + j * 3 + 1];
        const float dz = sm[OFF_CRD + i * 3 + 2] - sm[OFF_CRD + j * 3 + 2];
        sm[OFF_EA + idx] = dx * dx + dy * dy + dz * dz;
    }
    /* barrier after weight staging below orders EA before use */

    ull* const wbu = (ull*)(sm + OFF_WB) + (size_t)w * 8 * HN;

    for (int l = 0; l < LN; ++l) {
        /* ---- stage this layer's weights into shared ---- */
        {
            const float* s1 = ew1 + l * 130 * 64;
            for (int q = tid; q < 130 * 64; q += NTHREADS) sm[OFF_EW1 + q] = s1[q];
            const float* s2 = ew2 + l * 4096;
            for (int q = tid; q < 4096; q += NTHREADS) sm[OFF_EW2 + q] = s2[q];
            const float* s3 = nw1 + l * 8192;
            for (int q = tid; q < 8192; q += NTHREADS) sm[OFF_NW1 + q] = s3[q];
            const float* s4 = nw2 + l * 4096;
            for (int q = tid; q < 4096; q += NTHREADS) sm[OFF_NW2 + q] = s4[q];
            const float* s5 = cw1 + l * 4096;
            for (int q = tid; q < 4096; q += NTHREADS) sm[OFF_CW1 + q] = s5[q];
            if (tid < 64) {
                sm[OFF_CW2 + tid] = cw2[l * 64 + tid];
                sm[OFF_AW + tid]  = aw[l * 64 + tid];
                sm[OFF_EB1 + tid] = eb1[l * 64 + tid];
                sm[OFF_EB2 + tid] = eb2[l * 64 + tid];
                sm[OFF_NB1 + tid] = nb1[l * 64 + tid];
                sm[OFF_NB2 + tid] = nb2[l * 64 + tid];
                sm[OFF_CB1 + tid] = cb1[l * 64 + tid];
            }
            if (tid == 0) sm[OFF_AB] = ab[l];
        }
        __syncthreads();

        /* ---- phase 1: Hr = h@W1[0:64], Hc = h@W1[64:128] (packed) ---- */
#pragma unroll
        for (int nn = 0; nn < 2; ++nn) {
            const int i = w * 2 + nn;
            ull r2 = 0ull, c2 = 0ull;
#pragma unroll 8
            for (int k = 0; k < HN; ++k) {
                const float a = sm[OFF_H + i * HN + k];
                const ull ap = pack2(a, a);
                ffma2(r2, ap, *(const ull*)&sm[OFF_EW1 + k * HN + 2 * lane]);
                ffma2(c2, ap, *(const ull*)&sm[OFF_EW1 + (64 + k) * HN + 2 * lane]);
            }
            *(ull*)&sm[OFF_HR + i * HN + 2 * lane] = r2;
            *(ull*)&sm[OFF_HC + i * HN + 2 * lane] = c2;
        }
        __syncthreads();

        /* ---- phase 2: edges, 8 at a time per warp ---- */
        float aggL[2][2];
        float dcd[2][3];
        for (int nn = 0; nn < 2; ++nn) {
            const int i = w * 2 + nn;
            float agg0 = 0.f, agg1 = 0.f, dc0 = 0.f, dc1 = 0.f, dc2 = 0.f;
            const float cix = sm[OFF_CRD + i * 3 + 0];
            const float ciy = sm[OFF_CRD + i * 3 + 1];
            const float ciz = sm[OFF_CRD + i * 3 + 2];
            const ull hrp   = *(const ull*)&sm[OFF_HR + i * HN + 2 * lane];
            const ull w128p = *(const ull*)&sm[OFF_EW1 + 128 * HN + 2 * lane];
            const ull w129p = *(const ull*)&sm[OFF_EW1 + 129 * HN + 2 * lane];
            const ull b1p   = *(const ull*)&sm[OFF_EB1 + 2 * lane];
            const ull b2p   = *(const ull*)&sm[OFF_EB2 + 2 * lane];
            const ull cbp   = *(const ull*)&sm[OFF_CB1 + 2 * lane];
            const float aw0  = sm[OFF_AW + 2 * lane];
            const float aw1  = sm[OFF_AW + 2 * lane + 1];
            const float cw20 = sm[OFF_CW2 + 2 * lane];
            const float cw21 = sm[OFF_CW2 + 2 * lane + 1];
            const float abv  = sm[OFF_AB];

            for (int g = 0; g < 3; ++g) {
                float ndx[8], ndy[8], ndz[8];
                /* stage t1 = silu(e_in @ ew1 + eb1), duplicated {v,v} */
#pragma unroll
                for (int e = 0; e < 8; ++e) {
                    const int jraw = g * 8 + e;
                    int j = (jraw < i) ? jraw : jraw + 1;
                    if (j >= PN) j = i;               /* dummy self-edge */
                    const float dx = cix - sm[OFF_CRD + j * 3 + 0];
                    const float dy = ciy - sm[OFF_CRD + j * 3 + 1];
                    const float dz = ciz - sm[OFF_CRD + j * 3 + 2];
                    const float radial = dx * dx + dy * dy + dz * dz;
                    const float inv = 1.f / (sqrtf(radial) + 1.f);
                    ndx[e] = dx * inv; ndy[e] = dy * inv; ndz[e] = dz * inv;
                    const float eav = sm[OFF_EA + i * PN + j];
                    ull p = add2(add2(hrp, *(const ull*)&sm[OFF_HC + j * HN + 2 * lane]), b1p);
                    ffma2(p, pack2(radial, radial), w128p);
                    ffma2(p, pack2(eav, eav), w129p);
                    float p0, p1; unpack2(p, p0, p1);
                    const float v0 = siluf(p0), v1 = siluf(p1);
                    wbu[e * HN + 2 * lane]     = pack2(v0, v0);
                    wbu[e * HN + 2 * lane + 1] = pack2(v1, v1);
                }
                __syncwarp();

                /* GEMV2: m = silu(t1 @ ew2 + eb2) */
                ull u[8];
#pragma unroll
                for (int e = 0; e < 8; ++e) u[e] = b2p;
                gemv8(&sm[OFF_EW2], wbu, lane, u);

                float m0[8], m1[8], part[8];
#pragma unroll
                for (int e = 0; e < 8; ++e) {
                    float x0, x1; unpack2(u[e], x0, x1);
                    m0[e] = siluf(x0); m1[e] = siluf(x1);
                    part[e] = m0[e] * aw0 + m1[e] * aw1;
                }
#pragma unroll
                for (int off = 16; off; off >>= 1)
#pragma unroll
                    for (int e = 0; e < 8; ++e)
                        part[e] += __shfl_xor_sync(0xffffffffu, part[e], off);
#pragma unroll
                for (int e = 0; e < 8; ++e) {
                    const float gate = sigmf_(part[e] + abv);
                    m0[e] *= gate; m1[e] *= gate;
                }
                __syncwarp();   /* gemv2 reads of t1 complete */
#pragma unroll
                for (int e = 0; e < 8; ++e) {
                    wbu[e * HN + 2 * lane]     = pack2(m0[e], m0[e]);
                    wbu[e * HN + 2 * lane + 1] = pack2(m1[e], m1[e]);
                }
                __syncwarp();

                /* GEMV3: c1 = silu(m @ cw1 + cb1); scal = tanh(c1 @ cw2)*CR */
                ull q[8];
#pragma unroll
                for (int e = 0; e < 8; ++e) q[e] = cbp;
                gemv8(&sm[OFF_CW1], wbu, lane, q);

                float s[8];
#pragma unroll
                for (int e = 0; e < 8; ++e) {
                    float x0, x1; unpack2(q[e], x0, x1);
                    s[e] = siluf(x0) * cw20 + siluf(x1) * cw21;
                }
#pragma unroll
                for (int off = 16; off; off >>= 1)
#pragma unroll
                    for (int e = 0; e < 8; ++e)
                        s[e] += __shfl_xor_sync(0xffffffffu, s[e], off);
#pragma unroll
                for (int e = 0; e < 8; ++e) {
                    const float scal = tanhf(s[e]) * CRC;
                    dc0 += ndx[e] * scal;
                    dc1 += ndy[e] * scal;
                    dc2 += ndz[e] * scal;
                    if (g * 8 + e < PN - 1) { agg0 += m0[e]; agg1 += m1[e]; }
                }
                __syncwarp();   /* reads of m done before next group rewrites wbu */
            }
            aggL[nn][0] = agg0; aggL[nn][1] = agg1;
            dcd[nn][0] = dc0; dcd[nn][1] = dc1; dcd[nn][2] = dc2;
        }
        __syncthreads();   /* all reads of coord/Hr/Hc complete */

        /* ---- phase 3: coord update + node MLP (owner warp, no atomics) ---- */
        float* const wbf = (float*)wbu;
#pragma unroll
        for (int nn = 0; nn < 2; ++nn) {
            const int i = w * 2 + nn;
            if (lane == 0) {
                sm[OFF_CRD + i * 3 + 0] += dcd[nn][0];
                sm[OFF_CRD + i * 3 + 1] += dcd[nn][1];
                sm[OFF_CRD + i * 3 + 2] += dcd[nn][2];
            }
            wbf[2 * lane] = aggL[nn][0];
            wbf[2 * lane + 1] = aggL[nn][1];
            __syncwarp();
            ull g2 = *(const ull*)&sm[OFF_NB1 + 2 * lane];
#pragma unroll 8
            for (int k = 0; k < HN; ++k) {
                const float a = sm[OFF_H + i * HN + k];
                ffma2(g2, pack2(a, a), *(const ull*)&sm[OFF_NW1 + k * HN + 2 * lane]);
            }
#pragma unroll 8
            for (int k = 0; k < HN; ++k) {
                const float a = wbf[k];
                ffma2(g2, pack2(a, a), *(const ull*)&sm[OFF_NW1 + (HN + k) * HN + 2 * lane]);
            }
            float g0, g1; unpack2(g2, g0, g1);
            g0 = siluf(g0); g1 = siluf(g1);
            __syncwarp();
            wbf[2 * lane] = g0; wbf[2 * lane + 1] = g1;
            __syncwarp();
            ull o2 = *(const ull*)&sm[OFF_NB2 + 2 * lane];
#pragma unroll 8
            for (int k = 0; k < HN; ++k) {
                const float a = wbf[k];
                ffma2(o2, pack2(a, a), *(const ull*)&sm[OFF_NW2 + k * HN + 2 * lane]);
            }
            float o0, o1; unpack2(o2, o0, o1);
            sm[OFF_H + i * HN + 2 * lane]     += o0;
            sm[OFF_H + i * HN + 2 * lane + 1] += o1;
            __syncwarp();
        }
        __syncthreads();
    } /* layer loop */

    /* ---- velocity + mean removal ---- */
    for (int idx = tid; idx < PN * DN; idx += NTHREADS)
        sm[OFF_VEL + idx] = sm[OFF_CRD + idx] - sm[OFF_CR0 + idx];
    __syncthreads();
    if (tid < DN) {
        float s = 0.f;
        for (int i = 0; i < PN; ++i) s += sm[OFF_VEL + i * 3 + tid];
        sm[OFF_MEAN + tid] = s * (1.f / PN);
    }
    __syncthreads();
    for (int idx = tid; idx < PN * DN; idx += NTHREADS)
        out[b * (PN * DN) + idx] = sm[OFF_VEL + idx] - sm[OFF_MEAN + idx % 3];
}

extern "C" void kernel_launch(void* const* d_in, const int* in_sizes, int n_in,
                              void* d_out, int out_size)
{
    const float* t    = (const float*)d_in[0];
    const float* x    = (const float*)d_in[1];
    const float* embW = (const float*)d_in[2];
    const float* embb = (const float*)d_in[3];
    /* d_in[4] out_W, d_in[5] out_b: dead code (output depends only on coords) */
    const float* ew1  = (const float*)d_in[6];
    const float* eb1  = (const float*)d_in[7];
    const float* ew2  = (const float*)d_in[8];
    const float* eb2  = (const float*)d_in[9];
    const float* nw1  = (const float*)d_in[10];
    const float* nb1  = (const float*)d_in[11];
    const float* nw2  = (const float*)d_in[12];
    const float* nb2  = (const float*)d_in[13];
    const float* cw1  = (const float*)d_in[14];
    const float* cb1  = (const float*)d_in[15];
    const float* cw2  = (const float*)d_in[16];
    const float* aw   = (const float*)d_in[17];
    const float* ab   = (const float*)d_in[18];
    /* d_in[19] rows, d_in[20] cols: structure known analytically */

    const int B = in_sizes[0];
    const size_t smem = (size_t)SMEM_FLOATS * sizeof(float);
    cudaFuncSetAttribute(egnn_kernel, cudaFuncAttributeMaxDynamicSharedMemorySize, (int)smem);
    egnn_kernel<<<B, NTHREADS, smem>>>(t, x, embW, embb, ew1, eb1, ew2, eb2,
                                       nw1, nb1, nw2, nb2, cw1, cb1, cw2, aw, ab,
                                       (float*)d_out);
}